// round 9
// baseline (speedup 1.0000x reference)
#include <cuda_runtime.h>
#include <cuda_bf16.h>
#include <cstddef>

// Enframe: x (8,2,480000) f32 -> out (8,4096,934) f32
//   out[b, c*2048 + k, t] = x[b, c, t*512 + k]
// k = q*512 + r (q in [0,4), r in [0,512)), bc = b*2+c:
//   out[bc, q*512 + r, t] = x[bc, (t+q)*512 + r]
// R8 structure kept (tile 128t x 32r, 2048 blocks, MLP=5 load batch, __stcs).
// Store phase remapped: lane = single t -> LDS lane-stride = 1 smem row
// (33 floats, odd) = perfectly conflict-free, stores are coalesced STG.32.

#define S_LEN     480000
#define T_OUT     934          // (480000 - 2048)/512 + 1
#define SLOTS     937          // max slot = 933 + 3 = 936
#define ROWS      2048         // per-bc output rows
#define R_PAD     33
#define T_TILE    128
#define SLOT_NEED 131          // 128 t + q shift (3)

__global__ __launch_bounds__(256) void enframe_kernel(const float4* __restrict__ x4,
                                                      float* __restrict__ out) {
    __shared__ float tile[SLOT_NEED * R_PAD];   // 131*33*4 = 17292 B

    const int rt = blockIdx.x;   // 0..15  r base = rt*32
    const int tt = blockIdx.y;   // 0..7   t base = tt*128
    const int bc = blockIdx.z;   // 0..15
    const int tx = threadIdx.x;  // 0..31
    const int ty = threadIdx.y;  // 0..7

    const int tb = tt * T_TILE;
    const float4* __restrict__ xin = x4 + (size_t)bc * (S_LEN / 4);

    const bool interior = (tt < 7);     // t-tiles 0..6: no guards anywhere

    // ---- Load phase: issue all 5 LDG.128 first (MLP=5), then STS ----
    const int c    = tx & 7;            // float4 column: r = rt*32 + 4c + j
    const int lrow = ty * 4 + (tx >> 3);   // 0..31

    float4 v[5];
#pragma unroll
    for (int p = 0; p < 5; ++p) {
        const int row = p * 32 + lrow;
        v[p] = make_float4(0.f, 0.f, 0.f, 0.f);
        if (row < SLOT_NEED) {
            const int s = tb + row;
            if (interior || s < SLOTS) v[p] = xin[(size_t)s * 128 + rt * 8 + c];
        }
    }
#pragma unroll
    for (int p = 0; p < 5; ++p) {
        const int row = p * 32 + lrow;
        if (row < SLOT_NEED) {
            float* dst = &tile[row * R_PAD + 4 * c];   // conflict-free STS
            dst[0] = v[p].x; dst[1] = v[p].y; dst[2] = v[p].z; dst[3] = v[p].w;
        }
    }
    __syncthreads();

    // ---- Store phase: warp ty -> (q = ty>>1, seg pair = ty&1); lane = t ----
    const int q  = ty >> 1;
    const int sp = ty & 1;
    float* __restrict__ outb = out + (size_t)bc * ROWS * T_OUT
                                   + (size_t)(q * 512 + rt * 32) * T_OUT;

#pragma unroll
    for (int i = 0; i < 2; ++i) {
        const int seg = sp * 2 + i;            // 0..3 (32-t segment)
        const int t   = tb + seg * 32 + tx;    // consecutive t across lanes
        const int row = seg * 32 + tx + q;     // slot row for this t
        const float* __restrict__ src = &tile[row * R_PAD];

        if (interior || t < T_OUT) {
            float* o = outb + t;
#pragma unroll
            for (int rl = 0; rl < 32; ++rl) {
                // LDS: banks (33*row + rl) = (lane + rl) mod 32, conflict-free
                // STG.32: 32 consecutive t = 128B coalesced, evict-first
                __stcs(o + (size_t)rl * T_OUT, src[rl]);
            }
        }
    }
}

extern "C" void kernel_launch(void* const* d_in, const int* in_sizes, int n_in,
                              void* d_out, int out_size) {
    const float4* x = (const float4*)d_in[0];
    float* out = (float*)d_out;

    dim3 block(32, 8, 1);
    dim3 grid(16, 8, 16);   // (r tiles of 32, t tiles of 128, bc)
    enframe_kernel<<<grid, block>>>(x, out);
}

// round 10
// speedup vs baseline: 1.3751x; 1.3751x over previous
#include <cuda_runtime.h>
#include <cuda_bf16.h>
#include <cstddef>

// Enframe: x (8,2,480000) f32 -> out (8,4096,934) f32
//   out[bc, q*512 + r, t] = x[bc, (t+q)*512 + r],  bc = b*2+c, q in [0,4)
// R8 tile/grid and STORE pattern kept exactly (128t x 32r, 2048 blocks,
// MLP=5 load batch, STG.64 __stcs 256B runs). smem transposed to
// trans[r_local][slot] with XOR swizzle so pair reads are ONE conflict-free
// LDS.64 instead of two 2-phase LDS.32.

#define S_LEN     480000
#define T_OUT     934          // (480000 - 2048)/512 + 1
#define SLOTS     937
#define ROWS      2048
#define T_TILE    128
#define SLOT_TILE 132          // slots needed: 128 t + q(3) + lookahead(1)
#define SSTR      160          // slot stride (floats): 160 % 32 == 0, even

__global__ __launch_bounds__(256) void enframe_kernel(const float4* __restrict__ x4,
                                                      float* __restrict__ out) {
    __shared__ float trans[32 * SSTR];   // [r_local][slot ^ (r&28)] : 20480 B

    const int rt = blockIdx.x;   // 0..15  r base = rt*32
    const int tt = blockIdx.y;   // 0..7   t base = tt*128
    const int bc = blockIdx.z;   // 0..15
    const int tx = threadIdx.x;  // 0..31
    const int ty = threadIdx.y;  // 0..7

    const int tb = tt * T_TILE;
    const float4* __restrict__ xin = x4 + (size_t)bc * (S_LEN / 4);
    const bool interior = (tt < 7);

    // ---- Load phase: batch 5 LDG.128 (MLP=5), then swizzled STS ----
    const int c    = tx & 7;               // r group: r_local = 4c..4c+3
    const int lrow = ty * 4 + (tx >> 3);   // slot sub-index 0..31 per pass

    float4 v[5];
#pragma unroll
    for (int p = 0; p < 5; ++p) {
        const int sl = p * 32 + lrow;
        v[p] = make_float4(0.f, 0.f, 0.f, 0.f);
        if (sl < SLOT_TILE) {
            const int s = tb + sl;
            if (interior || s < SLOTS) v[p] = xin[(size_t)s * 128 + rt * 8 + c];
        }
    }
#pragma unroll
    for (int p = 0; p < 5; ++p) {
        const int sl = p * 32 + lrow;
        if (sl < SLOT_TILE) {
            const int sphys = sl ^ (4 * c);   // (4c+j)&28 == 4c for j<4
            // banks = (sl ^ 4c) mod 32 = 4*(ty^c) + rowoff: all 32 distinct
            trans[(4 * c + 0) * SSTR + sphys] = v[p].x;
            trans[(4 * c + 1) * SSTR + sphys] = v[p].y;
            trans[(4 * c + 2) * SSTR + sphys] = v[p].z;
            trans[(4 * c + 3) * SSTR + sphys] = v[p].w;
        }
    }
    __syncthreads();

    // ---- Store phase: warp ty -> (q = ty>>1, half = ty&1); lane = t pair ----
    const int q  = ty >> 1;
    const int h  = ty & 1;
    const int t_a = tb + h * 64 + 2 * tx;          // even t; pair (t_a, t_a+1)
    float* __restrict__ o0 = out + (size_t)bc * ROWS * T_OUT
                                 + (size_t)(q * 512 + rt * 32) * T_OUT + t_a;

    if (interior || t_a < T_OUT) {                 // pair valid: t_a<=932 -> t_b<=933
        if ((q & 1) == 0) {
            const int sb = h * 64 + 2 * tx + q;    // even slot base = t_a - tb + q
#pragma unroll
            for (int g = 0; g < 8; ++g) {
                const int sph = sb ^ (4 * g);      // swz const over 4-row group
#pragma unroll
                for (int i = 0; i < 4; ++i) {
                    const int rl = 4 * g + i;
                    // LDS.64: phase of 16 lanes covers all 32 banks
                    float2 w = *(const float2*)&trans[rl * SSTR + sph];
                    __stcs((float2*)(o0 + (size_t)rl * T_OUT), w);   // STG.64
                }
            }
        } else {
            const int sa = h * 64 + 2 * tx + q;    // odd slot for t_a
            const int e1 = sa - 1, e2 = sa + 1;    // even bases
#pragma unroll
            for (int g = 0; g < 8; ++g) {
                const int sph1 = e1 ^ (4 * g);
                const int sph2 = e2 ^ (4 * g);
#pragma unroll
                for (int i = 0; i < 4; ++i) {
                    const int rl = 4 * g + i;
                    const float2 w1 = *(const float2*)&trans[rl * SSTR + sph1];
                    const float2 w2 = *(const float2*)&trans[rl * SSTR + sph2];
                    const float2 w = make_float2(w1.y, w2.x);  // slots sa, sa+1
                    __stcs((float2*)(o0 + (size_t)rl * T_OUT), w);
                }
            }
        }
    }
}

extern "C" void kernel_launch(void* const* d_in, const int* in_sizes, int n_in,
                              void* d_out, int out_size) {
    const float4* x = (const float4*)d_in[0];
    float* out = (float*)d_out;

    dim3 block(32, 8, 1);
    dim3 grid(16, 8, 16);   // (r tiles of 32, t tiles of 128, bc)
    enframe_kernel<<<grid, block>>>(x, out);
}

// round 12
// speedup vs baseline: 1.4856x; 1.0803x over previous
#include <cuda_runtime.h>
#include <cuda_bf16.h>
#include <cstddef>

// Enframe: x (8,2,480000) f32 -> out (8,4096,934) f32
//   out[bc, q*512 + r, t] = x[bc, (t+q)*512 + r],  bc = b*2+c, q in [0,4)
// R8 structure (tile 128t x 32r, 2048 blocks, MLP=5 load batch, __stcs
// STG.64) + per-row t-window shift delta(row) = 2*(row mod 4) so every
// 256B store run starts 32B-sector-aligned
// (byte addr = 24*row + 4*t mod 32 == 0  <=>  t == 2*row mod 8).
// R11 fix: SLOT_NEED 136 -> 137 (max slot = t(133) + q(3) + pair(1)).

#define S_LEN     480000
#define T_OUT     934          // (480000 - 2048)/512 + 1
#define SLOTS     937          // max slot = 933 + 3 = 936
#define ROWS      2048         // per-bc output rows
#define R_PAD     33
#define T_TILE    128
#define SLOT_NEED 137          // 128 t + delta(6) + q(3) -> slot 136 inclusive

__global__ __launch_bounds__(256) void enframe_kernel(const float4* __restrict__ x4,
                                                      float* __restrict__ out) {
    __shared__ float tile[SLOT_NEED * R_PAD];   // 137*33*4 = 18084 B

    const int rt = blockIdx.x;   // 0..15  r base = rt*32
    const int tt = blockIdx.y;   // 0..7   t base = tt*128
    const int bc = blockIdx.z;   // 0..15
    const int tx = threadIdx.x;  // 0..31
    const int ty = threadIdx.y;  // 0..7

    const int tb = tt * T_TILE;
    const float4* __restrict__ xin = x4 + (size_t)bc * (S_LEN / 4);
    // interior tiles tt<7: max t = tb+133 <= 901 < 934, max s = tb+136 <= 904 < 937
    const bool interior = (tt < 7);

    // ---- Load phase: batch all 5 LDG.128 (MLP=5), then conflict-free STS ----
    const int c    = tx & 7;               // float4 column: r = rt*32 + 4c + j
    const int lrow = ty * 4 + (tx >> 3);   // 0..31

    float4 v[5];
#pragma unroll
    for (int p = 0; p < 5; ++p) {
        const int row = p * 32 + lrow;
        v[p] = make_float4(0.f, 0.f, 0.f, 0.f);
        if (row < SLOT_NEED) {
            const int s = tb + row;
            if (interior || s < SLOTS) v[p] = xin[(size_t)s * 128 + rt * 8 + c];
        }
    }
#pragma unroll
    for (int p = 0; p < 5; ++p) {
        const int row = p * 32 + lrow;
        if (row < SLOT_NEED) {
            float* dst = &tile[row * R_PAD + 4 * c];   // banks all distinct
            dst[0] = v[p].x; dst[1] = v[p].y; dst[2] = v[p].z; dst[3] = v[p].w;
        }
    }
    __syncthreads();

    // ---- Store phase: warp ty -> (q = ty>>1, half = ty&1); lane = t pair ----
    // Row rl has shift delta = 2*(rl mod 4); loop j = rl mod 4, m = rl / 4.
    const int q    = ty >> 1;
    const int half = ty & 1;
    const int t0   = tb + half * 64 + 2 * tx;   // even
    const int row0 = half * 64 + 2 * tx + q;    // slot row for t0

    float* __restrict__ outq = out + (size_t)bc * ROWS * T_OUT
                                   + (size_t)(q * 512 + rt * 32) * T_OUT;

#pragma unroll
    for (int j = 0; j < 4; ++j) {               // delta = 2j
        const int t = t0 + 2 * j;
        const float* __restrict__ src = &tile[(row0 + 2 * j) * R_PAD];
        if (interior || t < T_OUT) {            // t even, T_OUT even -> pair valid
            float* o = outq + (size_t)j * T_OUT + t;
#pragma unroll
            for (int m = 0; m < 8; ++m) {
                const int rl = 4 * m + j;       // rows with rl mod 4 == j
                float2 w;
                w.x = src[rl];                  // tile[row][rl]
                w.y = src[R_PAD + rl];          // tile[row+1][rl] -> t+1
                __stcs((float2*)(o + (size_t)(4 * m) * T_OUT), w);  // 32B-aligned run
            }
        }
    }

    // ---- tt==0: prepend uncovered heads t in [0, 2j) for rows rl == j (mod 4) ----
    if (tt == 0 && half == 0 && tx >= 29) {
        const int p = 31 - tx;                  // pair index 0..2
#pragma unroll
        for (int j = 1; j < 4; ++j) {
            if (p < j) {
                const int t = 2 * p;
                const float* __restrict__ src = &tile[(2 * p + q) * R_PAD];
                float* o = outq + (size_t)j * T_OUT + t;
#pragma unroll
                for (int m = 0; m < 8; ++m) {
                    const int rl = 4 * m + j;
                    float2 w;
                    w.x = src[rl];
                    w.y = src[R_PAD + rl];
                    __stcs((float2*)(o + (size_t)(4 * m) * T_OUT), w);
                }
            }
        }
    }
}

extern "C" void kernel_launch(void* const* d_in, const int* in_sizes, int n_in,
                              void* d_out, int out_size) {
    const float4* x = (const float4*)d_in[0];
    float* out = (float*)d_out;

    dim3 block(32, 8, 1);
    dim3 grid(16, 8, 16);   // (r tiles of 32, t tiles of 128, bc)
    enframe_kernel<<<grid, block>>>(x, out);
}